// round 15
// baseline (speedup 1.0000x reference)
#include <cuda_runtime.h>
#include <cuda_bf16.h>
#include <cstdint>

// LogSignature depth=4 of path (B=128, T=512, C=8).
// Output per batch: [L1(8) | L2(64) | L3(512) | L4(4096)] = 4680 floats.
//
// ROUND 15: k-pair-packed accumulators + duplicated-d shared array.
//   a2v[l][p] lanes = (a[k0+2p][l], a[k0+2p+1][l]).
//   Update: a2v[l][p] += (d_l,d_l) (x) g_pair  -- consumes g01/g23 in native
//   packed form; (d_l,d_l) read from s_dd (increments stored duplicated).
//   dk-pairs are one aligned ulonglong2 from the native row (no SEL).
//   Chen tree + log tail re-derived in k-pair form via transposed copies of
//   L3/L2 (sT3[(a*8+c)*8+b]=L3[a,b,c], sT2[c*8+b]=L2[b,c]) so every pair
//   read is a contiguous u64.
// Layout: 512 thr = 64 (i,j) x 2 k-halves x 4 segments (128 steps).

#define BATCH 128
#define TLEN  512
#define CH    8
#define NSTEP (TLEN - 1)
#define NSEG  4
#define SEGLEN 128
#define SEGSZ  (SEGLEN * CH + 8)    // native floats/seg (pad: banks + prefetch)
#define DSEGSZ (SEGLEN * CH + 2)    // dup u64/seg (pad: banks)
#define OUT_STRIDE 4680
#define OFF_L2 8
#define OFF_L3 72
#define OFF_L4 584

#define C3F (1.0f / 6.0f)
#define C4F (1.0f / 24.0f)

typedef unsigned long long u64;

__device__ __forceinline__ u64 ffma2(u64 a, u64 b, u64 c) {
    u64 d; asm("fma.rn.f32x2 %0, %1, %2, %3;" : "=l"(d) : "l"(a), "l"(b), "l"(c)); return d;
}
#define FFMA2_ACC(acc, a, b) \
    asm("fma.rn.f32x2 %0, %1, %2, %0;" : "+l"(acc) : "l"(a), "l"(b))
#define FADD2_ACC(acc, a) \
    asm("add.rn.f32x2 %0, %0, %1;" : "+l"(acc) : "l"(a))

__device__ __forceinline__ u64 pack2(float x, float y) {
    u64 d; asm("mov.b64 %0, {%1, %2};" : "=l"(d) : "f"(x), "f"(y)); return d;
}
__device__ __forceinline__ void unpack2(u64 a, float& x, float& y) {
    asm("mov.b64 {%0, %1}, %2;" : "=f"(x), "=f"(y) : "l"(a));
}

// dynamic shared layout (bytes)
#define DX_BYTES   (NSEG * SEGSZ * 4)            // 16512
#define DD_BYTES   (NSEG * DSEGSZ * 8)           // 32832
#define SL_STRIDE  584
#define ST3_STRIDE 516
#define ST2_STRIDE 68
#define SL_BYTES   (NSEG * SL_STRIDE * 4)        // 9344
#define ST3_BYTES  (NSEG * ST3_STRIDE * 4)       // 8256
#define ST2_BYTES  (NSEG * ST2_STRIDE * 4)       // 1088
#define SMEM_TOTAL (DX_BYTES + DD_BYTES + SL_BYTES + ST3_BYTES + ST2_BYTES)

__global__ void __launch_bounds__(512, 1)
logsig_kernel(const float* __restrict__ path, float* __restrict__ out)
{
    extern __shared__ __align__(16) unsigned char smem_raw[];
    float* s_dx = (float*)smem_raw;
    u64*   s_dd = (u64*)(smem_raw + DX_BYTES);
    float* sLb  = (float*)(smem_raw + DX_BYTES + DD_BYTES);
    float* sT3b = (float*)(smem_raw + DX_BYTES + DD_BYTES + SL_BYTES);
    float* sT2b = (float*)(smem_raw + DX_BYTES + DD_BYTES + SL_BYTES + ST3_BYTES);

    const int b   = blockIdx.x;
    const int tid = threadIdx.x;
    const float* p = path + (size_t)b * TLEN * CH;

    // increments: native (padded) + duplicated pairs; step 511 = zero
    for (int idx = tid; idx < NSEG * SEGLEN * CH; idx += 512) {
        const int tg = idx >> 3;
        const int c  = idx & 7;
        float v = 0.0f;
        if (tg < NSTEP) v = p[idx + CH] - p[idx];
        const int sg = tg >> 7, tl = tg & 127;
        s_dx[sg * SEGSZ + tl * CH + c]  = v;
        s_dd[sg * DSEGSZ + tl * CH + c] = pack2(v, v);
    }
    __syncthreads();

    const int s  = tid & 3;            // segment (lane bits 0..1: shfl tree)
    const int kh = (tid >> 2) & 1;     // k half
    const int ij = tid >> 3;           // 0..63
    const int i  = ij >> 3;
    const int j  = ij & 7;
    const int k0 = kh << 2;            // first owned k row

    u64 a2v[8][2];                     // [l][pair]; lanes (k0+2p, k0+2p+1)
    u64 r301 = 0, r323 = 0;            // r3 as k-pairs
    float r1 = 0.0f, r2 = 0.0f;
    #pragma unroll
    for (int l = 0; l < 8; ++l) { a2v[l][0] = 0; a2v[l][1] = 0; }

    // ---- scan own segment ----
    {
        const float* d  = &s_dx[s * SEGSZ];
        const u64*   dd = &s_dd[s * DSEGSZ];
        ulonglong2 dkp = *(const ulonglong2*)(d + k0);   // (dk0,dk1),(dk2,dk3)
        float di = d[i];
        float dj = d[j];

        #pragma unroll 1
        for (int t = 0; t < SEGLEN; ++t, d += CH, dd += CH) {
            const ulonglong2 D01 = *(const ulonglong2*)(dd + 0);  // (d0,d0),(d1,d1)
            const ulonglong2 D23 = *(const ulonglong2*)(dd + 2);
            const ulonglong2 D45 = *(const ulonglong2*)(dd + 4);
            const ulonglong2 D67 = *(const ulonglong2*)(dd + 6);

            // prefetch next row's critical values (pad absorbs over-read)
            const ulonglong2 ndkp = *(const ulonglong2*)(d + CH + k0);
            const float ndi = d[CH + i];
            const float ndj = d[CH + j];

            const float didj = di * dj;
            const float r1dj = r1 * dj;

            float ng = 0.5f * r2;
            ng = fmaf(C3F, r1dj, ng);
            ng = fmaf(C4F, didj, ng);
            float n2 = fmaf(0.5f, r1dj, r2);
            n2 = fmaf(C3F, didj, n2);
            const u64 ng2 = pack2(ng, ng);
            const u64 n22 = pack2(n2, n2);

            const u64 g01 = ffma2(ng2, dkp.x, r301);
            const u64 g23 = ffma2(ng2, dkp.y, r323);
            FFMA2_ACC(r301, n22, dkp.x);
            FFMA2_ACC(r323, n22, dkp.y);

            FFMA2_ACC(a2v[0][0], D01.x, g01);  FFMA2_ACC(a2v[0][1], D01.x, g23);
            FFMA2_ACC(a2v[1][0], D01.y, g01);  FFMA2_ACC(a2v[1][1], D01.y, g23);
            FFMA2_ACC(a2v[2][0], D23.x, g01);  FFMA2_ACC(a2v[2][1], D23.x, g23);
            FFMA2_ACC(a2v[3][0], D23.y, g01);  FFMA2_ACC(a2v[3][1], D23.y, g23);
            FFMA2_ACC(a2v[4][0], D45.x, g01);  FFMA2_ACC(a2v[4][1], D45.x, g23);
            FFMA2_ACC(a2v[5][0], D45.y, g01);  FFMA2_ACC(a2v[5][1], D45.y, g23);
            FFMA2_ACC(a2v[6][0], D67.x, g01);  FFMA2_ACC(a2v[6][1], D67.x, g23);
            FFMA2_ACC(a2v[7][0], D67.y, g01);  FFMA2_ACC(a2v[7][1], D67.y, g23);

            r2 = fmaf(0.5f, didj, r1dj) + r2;
            r1 += di;

            dkp = ndkp; di = ndi; dj = ndj;
        }
    }

    float* const sLs  = sLb  + s * SL_STRIDE;
    float* const sT3s = sT3b + s * ST3_STRIDE;
    float* const sT2s = sT2b + s * ST2_STRIDE;

    auto publish = [&](void) {
        *(u64*)&sLs[72 + ij * 8 + k0]     = r301;
        *(u64*)&sLs[72 + ij * 8 + k0 + 2] = r323;
        float t0, t1, t2, t3;
        unpack2(r301, t0, t1);
        unpack2(r323, t2, t3);
        sT3s[(i * 8 + k0 + 0) * 8 + j] = t0;   // sT3[(a*8+c)*8+b] = L3[a,b,c]
        sT3s[(i * 8 + k0 + 1) * 8 + j] = t1;
        sT3s[(i * 8 + k0 + 2) * 8 + j] = t2;
        sT3s[(i * 8 + k0 + 3) * 8 + j] = t3;
        if (kh == 0) { sLs[8 + ij] = r2; sT2s[j * 8 + i] = r2; }
        if (kh == 0 && j == 0) sLs[i] = r1;
    };
    publish();
    __syncthreads();

    // ---- 2-round Chen combine tree over segments ----
    #pragma unroll 1
    for (int r = 0; r < 2; ++r) {
        const int blk = 1 << r;
        const int Ab  = s & ~((blk << 1) - 1);
        const int Bb  = Ab + blk;
        const float* LA  = sLb  + Ab * SL_STRIDE;
        const float* LB  = sLb  + Bb * SL_STRIDE;
        const float* T3B = sT3b + Bb * ST3_STRIDE;
        const float* T2B = sT2b + Bb * ST2_STRIDE;

        const float A1  = LA[i];
        const float A2v = LA[8 + ij];
        const u64 A3a = *(const u64*)&LA[72 + ij * 8 + k0];
        const u64 A3b = *(const u64*)&LA[72 + ij * 8 + k0 + 2];
        const u64 A1d = pack2(A1, A1);
        const u64 A2d = pack2(A2v, A2v);

        const float c1  = A1 + LB[i];
        const float c2n = A2v + LB[8 + ij] + A1 * LB[j];

        // c3 pairs: S3 = A3 + B3 + A1*B2[j,k] + A2*B1[k]
        u64 c3a = A3a;
        FADD2_ACC(c3a, *(const u64*)&LB[72 + ij * 8 + k0]);
        FFMA2_ACC(c3a, A1d, *(const u64*)&LB[8 + j * 8 + k0]);
        FFMA2_ACC(c3a, A2d, *(const u64*)&LB[k0]);
        u64 c3b = A3b;
        FADD2_ACC(c3b, *(const u64*)&LB[72 + ij * 8 + k0 + 2]);
        FFMA2_ACC(c3b, A1d, *(const u64*)&LB[8 + j * 8 + k0 + 2]);
        FFMA2_ACC(c3b, A2d, *(const u64*)&LB[k0 + 2]);

        // L4 pairs: S4 = A4 + B4 + A1*B3[j,k,l] + A2*B2[k,l] + A3*B1[l]
        #pragma unroll
        for (int l = 0; l < 8; ++l) {
            const u64 S3p0 = *(const u64*)&T3B[(j * 8 + l) * 8 + k0];
            const u64 S3p1 = *(const u64*)&T3B[(j * 8 + l) * 8 + k0 + 2];
            const u64 S2p0 = *(const u64*)&T2B[l * 8 + k0];
            const u64 S2p1 = *(const u64*)&T2B[l * 8 + k0 + 2];
            const u64 B1dl = pack2(LB[l], LB[l]);

            u64 t0 = a2v[l][0];
            const u64 pr0 = __shfl_xor_sync(0xffffffffu, t0, blk);
            FADD2_ACC(t0, pr0);
            FFMA2_ACC(t0, A1d, S3p0);
            FFMA2_ACC(t0, A2d, S2p0);
            FFMA2_ACC(t0, A3a, B1dl);
            a2v[l][0] = t0;

            u64 t1 = a2v[l][1];
            const u64 pr1 = __shfl_xor_sync(0xffffffffu, t1, blk);
            FADD2_ACC(t1, pr1);
            FFMA2_ACC(t1, A1d, S3p1);
            FFMA2_ACC(t1, A2d, S2p1);
            FFMA2_ACC(t1, A3b, B1dl);
            a2v[l][1] = t1;
        }

        r1 = c1;
        r2 = c2n;
        r301 = c3a;
        r323 = c3b;

        __syncthreads();
        publish();
        __syncthreads();
    }

    // ---- closed-form log(1+x) truncated at depth 4 ----
    const float* L  = sLb;              // final combined (all slots equal)
    const float* T3 = sT3b;
    const float* T2 = sT2b;

    const float si = L[i];
    const float sj = L[j];
    const float sisj = si * sj;
    const float Qs = fmaf(1.0f / 3.0f, sisj, -0.5f * r2);
    const float Rs = -0.5f * si;
    const u64 Qd = pack2(Qs, Qs);
    const u64 Rd = pack2(Rs, Rs);

    float r3s[4];
    unpack2(r301, r3s[0], r3s[1]);
    unpack2(r323, r3s[2], r3s[3]);

    float Pv[4];
    #pragma unroll
    for (int kk = 0; kk < 4; ++kk) {
        const int k = k0 + kk;
        const float sk = L[k];
        const float s2jk = L[8 + j * 8 + k];
        const float cross = fmaf(si, s2jk, r2 * sk);
        const float sss = sisj * sk;
        Pv[kk] = fmaf(1.0f / 3.0f, cross, -0.5f * r3s[kk]) - 0.25f * sss;
    }
    const u64 Pp0 = pack2(Pv[0], Pv[1]);
    const u64 Pp1 = pack2(Pv[2], Pv[3]);

    #pragma unroll
    for (int l = 0; l < 8; ++l) {
        const u64 S1dl = pack2(L[l], L[l]);
        const u64 S2p0 = *(const u64*)&T2[l * 8 + k0];
        const u64 S2p1 = *(const u64*)&T2[l * 8 + k0 + 2];
        const u64 S3p0 = *(const u64*)&T3[(j * 8 + l) * 8 + k0];
        const u64 S3p1 = *(const u64*)&T3[(j * 8 + l) * 8 + k0 + 2];

        u64 t0 = a2v[l][0];
        FFMA2_ACC(t0, Pp0, S1dl);
        FFMA2_ACC(t0, Qd, S2p0);
        FFMA2_ACC(t0, Rd, S3p0);
        a2v[l][0] = t0;

        u64 t1 = a2v[l][1];
        FFMA2_ACC(t1, Pp1, S1dl);
        FFMA2_ACC(t1, Qd, S2p1);
        FFMA2_ACC(t1, Rd, S3p1);
        a2v[l][1] = t1;
    }

    // ---- stores: replica s writes L4/L3 row k_w = k0 + s ----
    float* ob = out + (size_t)b * OUT_STRIDE;
    const int pw  = s >> 1;
    const int par = s & 1;
    const int kw  = k0 + s;

    float row[8];
    #pragma unroll
    for (int l = 0; l < 8; ++l) {
        const u64 tv = pw ? a2v[l][1] : a2v[l][0];
        float lo, hi;
        unpack2(tv, lo, hi);
        row[l] = par ? hi : lo;
    }
    {
        float4 w0 = {row[0], row[1], row[2], row[3]};
        float4 w1 = {row[4], row[5], row[6], row[7]};
        *(float4*)(&ob[OFF_L4 + (ij * 8 + kw) * 8])     = w0;
        *(float4*)(&ob[OFF_L4 + (ij * 8 + kw) * 8 + 4]) = w1;
    }

    const float r3w = pw ? (par ? r3s[3] : r3s[2]) : (par ? r3s[1] : r3s[0]);
    const float skw = L[kw];
    const float s2jkw = L[8 + j * 8 + kw];
    const float crossw = fmaf(si, s2jkw, r2 * skw);
    const float sssw = sisj * skw;
    ob[OFF_L3 + ij * 8 + kw] = fmaf(1.0f / 3.0f, sssw, fmaf(-0.5f, crossw, r3w));

    if (s == 0 && kh == 0)
        ob[OFF_L2 + ij] = fmaf(-0.5f, sisj, r2);
    if (s == 0 && kh == 0 && j == 0)
        ob[i] = r1;
}

extern "C" void kernel_launch(void* const* d_in, const int* in_sizes, int n_in,
                              void* d_out, int out_size)
{
    const float* path = (const float*)d_in[0];
    float* out = (float*)d_out;
    cudaFuncSetAttribute(logsig_kernel,
                         cudaFuncAttributeMaxDynamicSharedMemorySize, SMEM_TOTAL);
    logsig_kernel<<<BATCH, 512, SMEM_TOTAL>>>(path, out);
}